// round 10
// baseline (speedup 1.0000x reference)
#include <cuda_runtime.h>

#define N_NODES  50000
#define N_EDGES  1600000
#define E_TOT    (N_EDGES + N_NODES)
#define N_GRAPHS 64

// ---------------- scratch (static __device__ — no allocations) ----------------
__device__ int   g_is64;
__device__ int   g_esrc[N_EDGES];
__device__ int   g_edst[N_EDGES];
__device__ int   g_batch[N_NODES];
__device__ int   g_deg[N_NODES];
__device__ int   g_rowptr[N_NODES + 1];
__device__ int   g_fill[N_NODES];
__device__ int   g_csr[E_TOT];
__device__ float g_xl1[N_NODES * 64];
__device__ float g_h1[N_NODES * 64];
__device__ float g_xl2[N_NODES * 128];
__device__ float g_as1[N_NODES * 2];
__device__ float g_ad1[N_NODES * 2];
__device__ float g_as2[N_NODES];
__device__ float g_ad2[N_NODES];
__device__ float g_pool[N_GRAPHS * 128];
__device__ int   g_cnt[N_GRAPHS];

// ---------------- dtype detection: int64 vs int32 edge_index ----------------
// If data is int64 (little-endian), every odd int32 word is the zero high-half
// (values are in [0, 50000)). If data is genuinely int32, the odd words are
// random indices; P(all 4096 sampled == 0) ~ 0.
__global__ void k_detect(const int* __restrict__ ei_i32) {
    __shared__ int sbad;
    if (threadIdx.x == 0) sbad = 0;
    __syncthreads();
    int bad = 0;
    for (int i = threadIdx.x; i < 4096; i += blockDim.x)
        if (ei_i32[2 * i + 1] != 0) bad = 1;
    if (bad) atomicOr(&sbad, 1);
    __syncthreads();
    if (threadIdx.x == 0) g_is64 = (sbad == 0) ? 1 : 0;
}

// ---------------- init (graph replays must re-zero everything) ----------------
__global__ void k_init() {
    int i = blockIdx.x * blockDim.x + threadIdx.x;
    if (i < N_NODES) g_deg[i] = 1;              // self-loop contributes 1
    if (i < N_GRAPHS * 128) g_pool[i] = 0.f;
    if (i < N_GRAPHS) g_cnt[i] = 0;
}

// ---------------- convert edges + dst histogram ----------------
__global__ void k_edges(const void* __restrict__ ei) {
    int e = blockIdx.x * blockDim.x + threadIdx.x;
    if (e >= N_EDGES) return;
    int s, d;
    if (g_is64) {
        const long long* p = (const long long*)ei;
        s = (int)p[e];
        d = (int)p[N_EDGES + e];
    } else {
        const int* p = (const int*)ei;
        s = p[e];
        d = p[N_EDGES + e];
    }
    g_esrc[e] = s;
    g_edst[e] = d;
    atomicAdd(&g_deg[d], 1);
}

// ---------------- convert batch + per-graph node counts ----------------
__global__ void k_batch(const void* __restrict__ b) {
    int i = blockIdx.x * blockDim.x + threadIdx.x;
    if (i >= N_NODES) return;
    int v = g_is64 ? (int)((const long long*)b)[i] : ((const int*)b)[i];
    g_batch[i] = v;
    atomicAdd(&g_cnt[v], 1);
}

// ---------------- single-block exclusive scan of degrees -> rowptr ----------------
__global__ void k_scan() {
    __shared__ int ssum[1024];
    int tid = threadIdx.x;
    const int chunk = (N_NODES + 1023) >> 10;   // 49
    int b = tid * chunk;
    int e = min(N_NODES, b + chunk);
    int s = 0;
    for (int i = b; i < e; i++) s += g_deg[i];
    ssum[tid] = s;
    __syncthreads();
    // Hillis-Steele inclusive scan
    for (int off = 1; off < 1024; off <<= 1) {
        int v = (tid >= off) ? ssum[tid - off] : 0;
        __syncthreads();
        ssum[tid] += v;
        __syncthreads();
    }
    int run = (tid == 0) ? 0 : ssum[tid - 1];
    for (int i = b; i < e; i++) {
        g_rowptr[i] = run;
        g_fill[i] = run;
        run += g_deg[i];
    }
    if (tid == 1023) g_rowptr[N_NODES] = run;   // total = E_TOT
}

// ---------------- scatter edges into dst-sorted CSR (incl. self-loops) ----------------
__global__ void k_scatter() {
    int e = blockIdx.x * blockDim.x + threadIdx.x;
    if (e < N_EDGES) {
        int d = g_edst[e];
        int pos = atomicAdd(&g_fill[d], 1);
        g_csr[pos] = g_esrc[e];
    } else if (e < E_TOT) {
        int n = e - N_EDGES;
        int pos = atomicAdd(&g_fill[n], 1);
        g_csr[pos] = n;
    }
}

// ---------------- layer 1 GEMM: xl1 = x @ W1 [N,128]x[128,64], + attn logits ----------------
__global__ void __launch_bounds__(256) k_gemm1(
    const float* __restrict__ x, const float* __restrict__ W1,
    const float* __restrict__ asw, const float* __restrict__ adw) {
    __shared__ float Ws[128 * 64];
    __shared__ float Xs[16 * 128];
    int t = threadIdx.x;
    for (int i = t; i < 128 * 64; i += 256) Ws[i] = W1[i];
    int n0 = blockIdx.x * 16;
    for (int i = t; i < 16 * 128; i += 256) {
        int nn = n0 + (i >> 7);
        Xs[i] = (nn < N_NODES) ? x[nn * 128 + (i & 127)] : 0.f;
    }
    __syncthreads();
    int c = t & 63, g = t >> 6;                 // node ni handled by 64 contiguous threads
    float a0 = 0, a1 = 0, a2 = 0, a3 = 0;
    const float* xs = &Xs[g * 4 * 128];
#pragma unroll 8
    for (int k = 0; k < 128; k++) {
        float w = Ws[k * 64 + c];
        a0 = fmaf(xs[k], w, a0);
        a1 = fmaf(xs[128 + k], w, a1);
        a2 = fmaf(xs[256 + k], w, a2);
        a3 = fmaf(xs[384 + k], w, a3);
    }
    float av = asw[c], dv = adw[c];             // att flattened [H*D]=64 matches channel c
    int h = c >> 5;
    float acc[4] = {a0, a1, a2, a3};
#pragma unroll
    for (int r = 0; r < 4; r++) {
        int node = n0 + g * 4 + r;
        float v = acc[r];
        float ps = v * av, pd = v * dv;
#pragma unroll
        for (int o = 16; o; o >>= 1) {
            ps += __shfl_xor_sync(0xffffffffu, ps, o);
            pd += __shfl_xor_sync(0xffffffffu, pd, o);
        }
        if (node < N_NODES) {
            g_xl1[node * 64 + c] = v;
            if ((c & 31) == 0) {                // lane 0 of each head's warp
                g_as1[node * 2 + h] = ps;
                g_ad1[node * 2 + h] = pd;
            }
        }
    }
}

// ---------------- layer 1 edge softmax + aggregate: one warp per dst node ----------------
__global__ void __launch_bounds__(256) k_edge1(const float* __restrict__ b1) {
    int wid = (blockIdx.x * blockDim.x + threadIdx.x) >> 5;
    int lane = threadIdx.x & 31;
    if (wid >= N_NODES) return;
    int dst = wid;
    int beg = g_rowptr[dst], end = g_rowptr[dst + 1];
    float2 adp = ((const float2*)g_ad1)[dst];
    float ad0 = adp.x, ad1 = adp.y;

    // pass 1: per-head max over incoming edges
    float m0 = -1e30f, m1 = -1e30f;
    for (int i = beg + lane; i < end; i += 32) {
        int s = g_csr[i];
        float2 as = ((const float2*)g_as1)[s];
        float e0 = as.x + ad0; e0 = e0 > 0.f ? e0 : 0.2f * e0;
        float e1 = as.y + ad1; e1 = e1 > 0.f ? e1 : 0.2f * e1;
        m0 = fmaxf(m0, e0);
        m1 = fmaxf(m1, e1);
    }
#pragma unroll
    for (int o = 16; o; o >>= 1) {
        m0 = fmaxf(m0, __shfl_xor_sync(0xffffffffu, m0, o));
        m1 = fmaxf(m1, __shfl_xor_sync(0xffffffffu, m1, o));
    }

    // pass 2: fused exp + denom + weighted aggregation (lane = channel)
    float acc0 = 0, acc1 = 0, den0 = 0, den1 = 0;
    for (int base = beg; base < end; base += 32) {
        int cnt = min(32, end - base);
        int sl = (lane < cnt) ? g_csr[base + lane] : 0;
        for (int j = 0; j < cnt; j++) {
            int s = __shfl_sync(0xffffffffu, sl, j);
            float2 as = ((const float2*)g_as1)[s];   // broadcast load
            float e0 = as.x + ad0; e0 = e0 > 0.f ? e0 : 0.2f * e0;
            float e1 = as.y + ad1; e1 = e1 > 0.f ? e1 : 0.2f * e1;
            float ex0 = __expf(e0 - m0);
            float ex1 = __expf(e1 - m1);
            den0 += ex0;
            den1 += ex1;
            const float* xr = &g_xl1[s * 64];
            acc0 = fmaf(ex0, xr[lane], acc0);
            acc1 = fmaf(ex1, xr[32 + lane], acc1);
        }
    }
    float o0 = acc0 / den0 + b1[lane];
    float o1 = acc1 / den1 + b1[32 + lane];
    o0 = o0 > 0.f ? o0 : expm1f(o0);            // ELU
    o1 = o1 > 0.f ? o1 : expm1f(o1);
    g_h1[dst * 64 + lane] = o0;
    g_h1[dst * 64 + 32 + lane] = o1;
}

// ---------------- layer 2 GEMM: xl2 = h1 @ W2 [N,64]x[64,128], + attn logits ----------------
__global__ void __launch_bounds__(256) k_gemm2(
    const float* __restrict__ W2,
    const float* __restrict__ asw, const float* __restrict__ adw) {
    __shared__ float Ws[64 * 128];
    __shared__ float Hs[8 * 64];
    __shared__ float sAS[8][4];
    __shared__ float sAD[8][4];
    int t = threadIdx.x;
    for (int i = t; i < 64 * 128; i += 256) Ws[i] = W2[i];
    int n0 = blockIdx.x * 8;
    for (int i = t; i < 8 * 64; i += 256) {
        int nn = n0 + (i >> 6);
        Hs[i] = (nn < N_NODES) ? g_h1[nn * 64 + (i & 63)] : 0.f;
    }
    __syncthreads();
    int c = t & 127, g = t >> 7;                // node handled by 128 contiguous threads
    float a[4] = {0, 0, 0, 0};
    const float* hs = &Hs[g * 4 * 64];
#pragma unroll 8
    for (int k = 0; k < 64; k++) {
        float w = Ws[k * 128 + c];
        a[0] = fmaf(hs[k], w, a[0]);
        a[1] = fmaf(hs[64 + k], w, a[1]);
        a[2] = fmaf(hs[128 + k], w, a[2]);
        a[3] = fmaf(hs[192 + k], w, a[3]);
    }
    float av = asw[c], dv = adw[c];
    int wim = (t >> 5) & 3;                     // warp within 128-thread node group
#pragma unroll
    for (int r = 0; r < 4; r++) {
        int node = n0 + g * 4 + r;
        float v = a[r];
        float ps = v * av, pd = v * dv;
#pragma unroll
        for (int o = 16; o; o >>= 1) {
            ps += __shfl_xor_sync(0xffffffffu, ps, o);
            pd += __shfl_xor_sync(0xffffffffu, pd, o);
        }
        if ((t & 31) == 0) {
            sAS[g * 4 + r][wim] = ps;
            sAD[g * 4 + r][wim] = pd;
        }
        if (node < N_NODES) g_xl2[node * 128 + c] = v;
    }
    __syncthreads();
    if (t < 8) {
        int node = n0 + t;
        if (node < N_NODES) {
            g_as2[node] = sAS[t][0] + sAS[t][1] + sAS[t][2] + sAS[t][3];
            g_ad2[node] = sAD[t][0] + sAD[t][1] + sAD[t][2] + sAD[t][3];
        }
    }
}

// ---------------- layer 2 edge softmax + aggregate + ELU + mean-pool scatter ----------------
__global__ void __launch_bounds__(256) k_edge2(const float* __restrict__ b2) {
    int wid = (blockIdx.x * blockDim.x + threadIdx.x) >> 5;
    int lane = threadIdx.x & 31;
    if (wid >= N_NODES) return;
    int dst = wid;
    int beg = g_rowptr[dst], end = g_rowptr[dst + 1];
    float ad = g_ad2[dst];

    float m = -1e30f;
    for (int i = beg + lane; i < end; i += 32) {
        int s = g_csr[i];
        float e = g_as2[s] + ad;
        e = e > 0.f ? e : 0.2f * e;
        m = fmaxf(m, e);
    }
#pragma unroll
    for (int o = 16; o; o >>= 1) m = fmaxf(m, __shfl_xor_sync(0xffffffffu, m, o));

    float acc0 = 0, acc1 = 0, acc2 = 0, acc3 = 0, den = 0;
    for (int base = beg; base < end; base += 32) {
        int cnt = min(32, end - base);
        int sl = (lane < cnt) ? g_csr[base + lane] : 0;
        for (int j = 0; j < cnt; j++) {
            int s = __shfl_sync(0xffffffffu, sl, j);
            float e = g_as2[s] + ad;
            e = e > 0.f ? e : 0.2f * e;
            float ex = __expf(e - m);
            den += ex;
            const float* xr = &g_xl2[s * 128];
            acc0 = fmaf(ex, xr[lane], acc0);
            acc1 = fmaf(ex, xr[32 + lane], acc1);
            acc2 = fmaf(ex, xr[64 + lane], acc2);
            acc3 = fmaf(ex, xr[96 + lane], acc3);
        }
    }
    float inv = 1.f / den;
    float o0 = acc0 * inv + b2[lane];       o0 = o0 > 0.f ? o0 : expm1f(o0);
    float o1 = acc1 * inv + b2[32 + lane];  o1 = o1 > 0.f ? o1 : expm1f(o1);
    float o2 = acc2 * inv + b2[64 + lane];  o2 = o2 > 0.f ? o2 : expm1f(o2);
    float o3 = acc3 * inv + b2[96 + lane];  o3 = o3 > 0.f ? o3 : expm1f(o3);

    float* p = &g_pool[g_batch[dst] * 128];
    atomicAdd(&p[lane], o0);
    atomicAdd(&p[32 + lane], o1);
    atomicAdd(&p[64 + lane], o2);
    atomicAdd(&p[96 + lane], o3);
}

// ---------------- finalize: mean pool ----------------
__global__ void k_final(float* __restrict__ out) {
    int i = blockIdx.x * blockDim.x + threadIdx.x;
    if (i >= N_GRAPHS * 128) return;
    float c = (float)g_cnt[i >> 7];
    out[i] = g_pool[i] / fmaxf(c, 1.f);
}

// ---------------- launch ----------------
extern "C" void kernel_launch(void* const* d_in, const int* in_sizes, int n_in,
                              void* d_out, int out_size) {
    const float* x   = (const float*)d_in[0];
    const void*  ei  = d_in[1];
    const void*  bat = d_in[2];
    const float* W1  = (const float*)d_in[3];
    const float* as1 = (const float*)d_in[4];
    const float* ad1 = (const float*)d_in[5];
    const float* b1  = (const float*)d_in[6];
    const float* W2  = (const float*)d_in[7];
    const float* as2 = (const float*)d_in[8];
    const float* ad2 = (const float*)d_in[9];
    const float* b2  = (const float*)d_in[10];
    float* out = (float*)d_out;

    k_detect<<<1, 256>>>((const int*)ei);
    k_init<<<(N_NODES + 255) / 256, 256>>>();
    k_edges<<<(N_EDGES + 255) / 256, 256>>>(ei);
    k_batch<<<(N_NODES + 255) / 256, 256>>>(bat);
    k_scan<<<1, 1024>>>();
    k_scatter<<<(E_TOT + 255) / 256, 256>>>();
    k_gemm1<<<(N_NODES + 15) / 16, 256>>>(x, W1, as1, ad1);
    k_edge1<<<(N_NODES * 32 + 255) / 256, 256>>>(b1);
    k_gemm2<<<(N_NODES + 7) / 8, 256>>>(W2, as2, ad2);
    k_edge2<<<(N_NODES * 32 + 255) / 256, 256>>>(b2);
    k_final<<<(N_GRAPHS * 128 + 255) / 256, 256>>>(out);
}

// round 11
// speedup vs baseline: 1.0053x; 1.0053x over previous
#include <cuda_runtime.h>

#define N_NODES  50000
#define N_EDGES  1600000
#define E_TOT    (N_EDGES + N_NODES)
#define N_GRAPHS 64

// ---------------- scratch (static __device__ — no allocations) ----------------
__device__ int   g_is64;
__device__ int   g_esrc[N_EDGES];
__device__ int   g_edst[N_EDGES];
__device__ int   g_batch[N_NODES];
__device__ int   g_deg[N_NODES];
__device__ int   g_rowptr[N_NODES + 1];
__device__ int   g_fill[N_NODES];
__device__ int   g_csr[E_TOT];
__device__ float g_xl1[N_NODES * 64];
__device__ float g_h1[N_NODES * 64];
__device__ float g_xl2[N_NODES * 128];
__device__ float g_as1[N_NODES * 2];
__device__ float g_ad1[N_NODES * 2];
__device__ float g_as2[N_NODES];
__device__ float g_ad2[N_NODES];
__device__ float g_pool[N_GRAPHS * 128];
__device__ int   g_cnt[N_GRAPHS];

// ---------------- dtype detection: int64 vs int32 edge_index ----------------
// If data is int64 (little-endian), every odd int32 word is the zero high-half
// (values are in [0, 50000)). If data is genuinely int32, the odd words are
// random indices; P(all 4096 sampled == 0) ~ 0.
__global__ void k_detect(const int* __restrict__ ei_i32) {
    __shared__ int sbad;
    if (threadIdx.x == 0) sbad = 0;
    __syncthreads();
    int bad = 0;
    for (int i = threadIdx.x; i < 4096; i += blockDim.x)
        if (ei_i32[2 * i + 1] != 0) bad = 1;
    if (bad) atomicOr(&sbad, 1);
    __syncthreads();
    if (threadIdx.x == 0) g_is64 = (sbad == 0) ? 1 : 0;
}

// ---------------- init (graph replays must re-zero everything) ----------------
__global__ void k_init() {
    int i = blockIdx.x * blockDim.x + threadIdx.x;
    if (i < N_NODES) g_deg[i] = 1;              // self-loop contributes 1
    if (i < N_GRAPHS * 128) g_pool[i] = 0.f;
    if (i < N_GRAPHS) g_cnt[i] = 0;
}

// ---------------- convert edges + dst histogram ----------------
__global__ void k_edges(const void* __restrict__ ei) {
    int e = blockIdx.x * blockDim.x + threadIdx.x;
    if (e >= N_EDGES) return;
    int s, d;
    if (g_is64) {
        const long long* p = (const long long*)ei;
        s = (int)p[e];
        d = (int)p[N_EDGES + e];
    } else {
        const int* p = (const int*)ei;
        s = p[e];
        d = p[N_EDGES + e];
    }
    g_esrc[e] = s;
    g_edst[e] = d;
    atomicAdd(&g_deg[d], 1);
}

// ---------------- convert batch + per-graph node counts ----------------
__global__ void k_batch(const void* __restrict__ b) {
    int i = blockIdx.x * blockDim.x + threadIdx.x;
    if (i >= N_NODES) return;
    int v = g_is64 ? (int)((const long long*)b)[i] : ((const int*)b)[i];
    g_batch[i] = v;
    atomicAdd(&g_cnt[v], 1);
}

// ---------------- single-block exclusive scan of degrees -> rowptr ----------------
__global__ void k_scan() {
    __shared__ int ssum[1024];
    int tid = threadIdx.x;
    const int chunk = (N_NODES + 1023) >> 10;   // 49
    int b = tid * chunk;
    int e = min(N_NODES, b + chunk);
    int s = 0;
    for (int i = b; i < e; i++) s += g_deg[i];
    ssum[tid] = s;
    __syncthreads();
    // Hillis-Steele inclusive scan
    for (int off = 1; off < 1024; off <<= 1) {
        int v = (tid >= off) ? ssum[tid - off] : 0;
        __syncthreads();
        ssum[tid] += v;
        __syncthreads();
    }
    int run = (tid == 0) ? 0 : ssum[tid - 1];
    for (int i = b; i < e; i++) {
        g_rowptr[i] = run;
        g_fill[i] = run;
        run += g_deg[i];
    }
    if (tid == 1023) g_rowptr[N_NODES] = run;   // total = E_TOT
}

// ---------------- scatter edges into dst-sorted CSR (incl. self-loops) ----------------
__global__ void k_scatter() {
    int e = blockIdx.x * blockDim.x + threadIdx.x;
    if (e < N_EDGES) {
        int d = g_edst[e];
        int pos = atomicAdd(&g_fill[d], 1);
        g_csr[pos] = g_esrc[e];
    } else if (e < E_TOT) {
        int n = e - N_EDGES;
        int pos = atomicAdd(&g_fill[n], 1);
        g_csr[pos] = n;
    }
}

// ---------------- layer 1 GEMM: xl1 = x @ W1 [N,128]x[128,64], + attn logits ----------------
__global__ void __launch_bounds__(256) k_gemm1(
    const float* __restrict__ x, const float* __restrict__ W1,
    const float* __restrict__ asw, const float* __restrict__ adw) {
    __shared__ float Ws[128 * 64];
    __shared__ float Xs[16 * 128];
    int t = threadIdx.x;
    for (int i = t; i < 128 * 64; i += 256) Ws[i] = W1[i];
    int n0 = blockIdx.x * 16;
    for (int i = t; i < 16 * 128; i += 256) {
        int nn = n0 + (i >> 7);
        Xs[i] = (nn < N_NODES) ? x[nn * 128 + (i & 127)] : 0.f;
    }
    __syncthreads();
    int c = t & 63, g = t >> 6;                 // node ni handled by 64 contiguous threads
    float a0 = 0, a1 = 0, a2 = 0, a3 = 0;
    const float* xs = &Xs[g * 4 * 128];
#pragma unroll 8
    for (int k = 0; k < 128; k++) {
        float w = Ws[k * 64 + c];
        a0 = fmaf(xs[k], w, a0);
        a1 = fmaf(xs[128 + k], w, a1);
        a2 = fmaf(xs[256 + k], w, a2);
        a3 = fmaf(xs[384 + k], w, a3);
    }
    float av = asw[c], dv = adw[c];             // att flattened [H*D]=64 matches channel c
    int h = c >> 5;
    float acc[4] = {a0, a1, a2, a3};
#pragma unroll
    for (int r = 0; r < 4; r++) {
        int node = n0 + g * 4 + r;
        float v = acc[r];
        float ps = v * av, pd = v * dv;
#pragma unroll
        for (int o = 16; o; o >>= 1) {
            ps += __shfl_xor_sync(0xffffffffu, ps, o);
            pd += __shfl_xor_sync(0xffffffffu, pd, o);
        }
        if (node < N_NODES) {
            g_xl1[node * 64 + c] = v;
            if ((c & 31) == 0) {                // lane 0 of each head's warp
                g_as1[node * 2 + h] = ps;
                g_ad1[node * 2 + h] = pd;
            }
        }
    }
}

// ---------------- layer 1 edge softmax + aggregate: one warp per dst node ----------------
__global__ void __launch_bounds__(256) k_edge1(const float* __restrict__ b1) {
    int wid = (blockIdx.x * blockDim.x + threadIdx.x) >> 5;
    int lane = threadIdx.x & 31;
    if (wid >= N_NODES) return;
    int dst = wid;
    int beg = g_rowptr[dst], end = g_rowptr[dst + 1];
    float2 adp = ((const float2*)g_ad1)[dst];
    float ad0 = adp.x, ad1 = adp.y;

    // pass 1: per-head max over incoming edges
    float m0 = -1e30f, m1 = -1e30f;
    for (int i = beg + lane; i < end; i += 32) {
        int s = g_csr[i];
        float2 as = ((const float2*)g_as1)[s];
        float e0 = as.x + ad0; e0 = e0 > 0.f ? e0 : 0.2f * e0;
        float e1 = as.y + ad1; e1 = e1 > 0.f ? e1 : 0.2f * e1;
        m0 = fmaxf(m0, e0);
        m1 = fmaxf(m1, e1);
    }
#pragma unroll
    for (int o = 16; o; o >>= 1) {
        m0 = fmaxf(m0, __shfl_xor_sync(0xffffffffu, m0, o));
        m1 = fmaxf(m1, __shfl_xor_sync(0xffffffffu, m1, o));
    }

    // pass 2: fused exp + denom + weighted aggregation (lane = channel)
    float acc0 = 0, acc1 = 0, den0 = 0, den1 = 0;
    for (int base = beg; base < end; base += 32) {
        int cnt = min(32, end - base);
        int sl = (lane < cnt) ? g_csr[base + lane] : 0;
        for (int j = 0; j < cnt; j++) {
            int s = __shfl_sync(0xffffffffu, sl, j);
            float2 as = ((const float2*)g_as1)[s];   // broadcast load
            float e0 = as.x + ad0; e0 = e0 > 0.f ? e0 : 0.2f * e0;
            float e1 = as.y + ad1; e1 = e1 > 0.f ? e1 : 0.2f * e1;
            float ex0 = __expf(e0 - m0);
            float ex1 = __expf(e1 - m1);
            den0 += ex0;
            den1 += ex1;
            const float* xr = &g_xl1[s * 64];
            acc0 = fmaf(ex0, xr[lane], acc0);
            acc1 = fmaf(ex1, xr[32 + lane], acc1);
        }
    }
    float o0 = acc0 / den0 + b1[lane];
    float o1 = acc1 / den1 + b1[32 + lane];
    o0 = o0 > 0.f ? o0 : expm1f(o0);            // ELU
    o1 = o1 > 0.f ? o1 : expm1f(o1);
    g_h1[dst * 64 + lane] = o0;
    g_h1[dst * 64 + 32 + lane] = o1;
}

// ---------------- layer 2 GEMM: xl2 = h1 @ W2 [N,64]x[64,128], + attn logits ----------------
__global__ void __launch_bounds__(256) k_gemm2(
    const float* __restrict__ W2,
    const float* __restrict__ asw, const float* __restrict__ adw) {
    __shared__ float Ws[64 * 128];
    __shared__ float Hs[8 * 64];
    __shared__ float sAS[8][4];
    __shared__ float sAD[8][4];
    int t = threadIdx.x;
    for (int i = t; i < 64 * 128; i += 256) Ws[i] = W2[i];
    int n0 = blockIdx.x * 8;
    for (int i = t; i < 8 * 64; i += 256) {
        int nn = n0 + (i >> 6);
        Hs[i] = (nn < N_NODES) ? g_h1[nn * 64 + (i & 63)] : 0.f;
    }
    __syncthreads();
    int c = t & 127, g = t >> 7;                // node handled by 128 contiguous threads
    float a[4] = {0, 0, 0, 0};
    const float* hs = &Hs[g * 4 * 64];
#pragma unroll 8
    for (int k = 0; k < 64; k++) {
        float w = Ws[k * 128 + c];
        a[0] = fmaf(hs[k], w, a[0]);
        a[1] = fmaf(hs[64 + k], w, a[1]);
        a[2] = fmaf(hs[128 + k], w, a[2]);
        a[3] = fmaf(hs[192 + k], w, a[3]);
    }
    float av = asw[c], dv = adw[c];
    int wim = (t >> 5) & 3;                     // warp within 128-thread node group
#pragma unroll
    for (int r = 0; r < 4; r++) {
        int node = n0 + g * 4 + r;
        float v = a[r];
        float ps = v * av, pd = v * dv;
#pragma unroll
        for (int o = 16; o; o >>= 1) {
            ps += __shfl_xor_sync(0xffffffffu, ps, o);
            pd += __shfl_xor_sync(0xffffffffu, pd, o);
        }
        if ((t & 31) == 0) {
            sAS[g * 4 + r][wim] = ps;
            sAD[g * 4 + r][wim] = pd;
        }
        if (node < N_NODES) g_xl2[node * 128 + c] = v;
    }
    __syncthreads();
    if (t < 8) {
        int node = n0 + t;
        if (node < N_NODES) {
            g_as2[node] = sAS[t][0] + sAS[t][1] + sAS[t][2] + sAS[t][3];
            g_ad2[node] = sAD[t][0] + sAD[t][1] + sAD[t][2] + sAD[t][3];
        }
    }
}

// ---------------- layer 2 edge softmax + aggregate + ELU + mean-pool scatter ----------------
__global__ void __launch_bounds__(256) k_edge2(const float* __restrict__ b2) {
    int wid = (blockIdx.x * blockDim.x + threadIdx.x) >> 5;
    int lane = threadIdx.x & 31;
    if (wid >= N_NODES) return;
    int dst = wid;
    int beg = g_rowptr[dst], end = g_rowptr[dst + 1];
    float ad = g_ad2[dst];

    float m = -1e30f;
    for (int i = beg + lane; i < end; i += 32) {
        int s = g_csr[i];
        float e = g_as2[s] + ad;
        e = e > 0.f ? e : 0.2f * e;
        m = fmaxf(m, e);
    }
#pragma unroll
    for (int o = 16; o; o >>= 1) m = fmaxf(m, __shfl_xor_sync(0xffffffffu, m, o));

    float acc0 = 0, acc1 = 0, acc2 = 0, acc3 = 0, den = 0;
    for (int base = beg; base < end; base += 32) {
        int cnt = min(32, end - base);
        int sl = (lane < cnt) ? g_csr[base + lane] : 0;
        for (int j = 0; j < cnt; j++) {
            int s = __shfl_sync(0xffffffffu, sl, j);
            float e = g_as2[s] + ad;
            e = e > 0.f ? e : 0.2f * e;
            float ex = __expf(e - m);
            den += ex;
            const float* xr = &g_xl2[s * 128];
            acc0 = fmaf(ex, xr[lane], acc0);
            acc1 = fmaf(ex, xr[32 + lane], acc1);
            acc2 = fmaf(ex, xr[64 + lane], acc2);
            acc3 = fmaf(ex, xr[96 + lane], acc3);
        }
    }
    float inv = 1.f / den;
    float o0 = acc0 * inv + b2[lane];       o0 = o0 > 0.f ? o0 : expm1f(o0);
    float o1 = acc1 * inv + b2[32 + lane];  o1 = o1 > 0.f ? o1 : expm1f(o1);
    float o2 = acc2 * inv + b2[64 + lane];  o2 = o2 > 0.f ? o2 : expm1f(o2);
    float o3 = acc3 * inv + b2[96 + lane];  o3 = o3 > 0.f ? o3 : expm1f(o3);

    float* p = &g_pool[g_batch[dst] * 128];
    atomicAdd(&p[lane], o0);
    atomicAdd(&p[32 + lane], o1);
    atomicAdd(&p[64 + lane], o2);
    atomicAdd(&p[96 + lane], o3);
}

// ---------------- finalize: mean pool ----------------
__global__ void k_final(float* __restrict__ out) {
    int i = blockIdx.x * blockDim.x + threadIdx.x;
    if (i >= N_GRAPHS * 128) return;
    float c = (float)g_cnt[i >> 7];
    out[i] = g_pool[i] / fmaxf(c, 1.f);
}

// ---------------- launch ----------------
extern "C" void kernel_launch(void* const* d_in, const int* in_sizes, int n_in,
                              void* d_out, int out_size) {
    const float* x   = (const float*)d_in[0];
    const void*  ei  = d_in[1];
    const void*  bat = d_in[2];
    const float* W1  = (const float*)d_in[3];
    const float* as1 = (const float*)d_in[4];
    const float* ad1 = (const float*)d_in[5];
    const float* b1  = (const float*)d_in[6];
    const float* W2  = (const float*)d_in[7];
    const float* as2 = (const float*)d_in[8];
    const float* ad2 = (const float*)d_in[9];
    const float* b2  = (const float*)d_in[10];
    float* out = (float*)d_out;

    k_detect<<<1, 256>>>((const int*)ei);
    k_init<<<(N_NODES + 255) / 256, 256>>>();
    k_edges<<<(N_EDGES + 255) / 256, 256>>>(ei);
    k_batch<<<(N_NODES + 255) / 256, 256>>>(bat);
    k_scan<<<1, 1024>>>();
    k_scatter<<<(E_TOT + 255) / 256, 256>>>();
    k_gemm1<<<(N_NODES + 15) / 16, 256>>>(x, W1, as1, ad1);
    k_edge1<<<(N_NODES * 32 + 255) / 256, 256>>>(b1);
    k_gemm2<<<(N_NODES + 7) / 8, 256>>>(W2, as2, ad2);
    k_edge2<<<(N_NODES * 32 + 255) / 256, 256>>>(b2);
    k_final<<<(N_GRAPHS * 128 + 255) / 256, 256>>>(out);
}

// round 12
// speedup vs baseline: 1.0061x; 1.0008x over previous
#include <cuda_runtime.h>

#define N_NODES  50000
#define N_EDGES  1600000
#define E_TOT    (N_EDGES + N_NODES)
#define N_GRAPHS 64

// ---------------- scratch (static __device__ — no allocations) ----------------
__device__ int   g_is64;
__device__ int   g_esrc[N_EDGES];
__device__ int   g_edst[N_EDGES];
__device__ int   g_batch[N_NODES];
__device__ int   g_deg[N_NODES];
__device__ int   g_rowptr[N_NODES + 1];
__device__ int   g_fill[N_NODES];
__device__ int   g_csr[E_TOT];
__device__ float g_xl1[N_NODES * 64];
__device__ float g_h1[N_NODES * 64];
__device__ float g_xl2[N_NODES * 128];
__device__ float g_as1[N_NODES * 2];
__device__ float g_ad1[N_NODES * 2];
__device__ float g_as2[N_NODES];
__device__ float g_ad2[N_NODES];
__device__ float g_pool[N_GRAPHS * 128];
__device__ int   g_cnt[N_GRAPHS];

// ---------------- dtype detection: int64 vs int32 edge_index ----------------
// If data is int64 (little-endian), every odd int32 word is the zero high-half
// (values are in [0, 50000)). If data is genuinely int32, the odd words are
// random indices; P(all 4096 sampled == 0) ~ 0.
__global__ void k_detect(const int* __restrict__ ei_i32) {
    __shared__ int sbad;
    if (threadIdx.x == 0) sbad = 0;
    __syncthreads();
    int bad = 0;
    for (int i = threadIdx.x; i < 4096; i += blockDim.x)
        if (ei_i32[2 * i + 1] != 0) bad = 1;
    if (bad) atomicOr(&sbad, 1);
    __syncthreads();
    if (threadIdx.x == 0) g_is64 = (sbad == 0) ? 1 : 0;
}

// ---------------- init (graph replays must re-zero everything) ----------------
__global__ void k_init() {
    int i = blockIdx.x * blockDim.x + threadIdx.x;
    if (i < N_NODES) g_deg[i] = 1;              // self-loop contributes 1
    if (i < N_GRAPHS * 128) g_pool[i] = 0.f;
    if (i < N_GRAPHS) g_cnt[i] = 0;
}

// ---------------- convert edges + dst histogram ----------------
__global__ void k_edges(const void* __restrict__ ei) {
    int e = blockIdx.x * blockDim.x + threadIdx.x;
    if (e >= N_EDGES) return;
    int s, d;
    if (g_is64) {
        const long long* p = (const long long*)ei;
        s = (int)p[e];
        d = (int)p[N_EDGES + e];
    } else {
        const int* p = (const int*)ei;
        s = p[e];
        d = p[N_EDGES + e];
    }
    g_esrc[e] = s;
    g_edst[e] = d;
    atomicAdd(&g_deg[d], 1);
}

// ---------------- convert batch + per-graph node counts ----------------
__global__ void k_batch(const void* __restrict__ b) {
    int i = blockIdx.x * blockDim.x + threadIdx.x;
    if (i >= N_NODES) return;
    int v = g_is64 ? (int)((const long long*)b)[i] : ((const int*)b)[i];
    g_batch[i] = v;
    atomicAdd(&g_cnt[v], 1);
}

// ---------------- single-block exclusive scan of degrees -> rowptr ----------------
__global__ void k_scan() {
    __shared__ int ssum[1024];
    int tid = threadIdx.x;
    const int chunk = (N_NODES + 1023) >> 10;   // 49
    int b = tid * chunk;
    int e = min(N_NODES, b + chunk);
    int s = 0;
    for (int i = b; i < e; i++) s += g_deg[i];
    ssum[tid] = s;
    __syncthreads();
    // Hillis-Steele inclusive scan
    for (int off = 1; off < 1024; off <<= 1) {
        int v = (tid >= off) ? ssum[tid - off] : 0;
        __syncthreads();
        ssum[tid] += v;
        __syncthreads();
    }
    int run = (tid == 0) ? 0 : ssum[tid - 1];
    for (int i = b; i < e; i++) {
        g_rowptr[i] = run;
        g_fill[i] = run;
        run += g_deg[i];
    }
    if (tid == 1023) g_rowptr[N_NODES] = run;   // total = E_TOT
}

// ---------------- scatter edges into dst-sorted CSR (incl. self-loops) ----------------
__global__ void k_scatter() {
    int e = blockIdx.x * blockDim.x + threadIdx.x;
    if (e < N_EDGES) {
        int d = g_edst[e];
        int pos = atomicAdd(&g_fill[d], 1);
        g_csr[pos] = g_esrc[e];
    } else if (e < E_TOT) {
        int n = e - N_EDGES;
        int pos = atomicAdd(&g_fill[n], 1);
        g_csr[pos] = n;
    }
}

// ---------------- layer 1 GEMM: xl1 = x @ W1 [N,128]x[128,64], + attn logits ----------------
__global__ void __launch_bounds__(256) k_gemm1(
    const float* __restrict__ x, const float* __restrict__ W1,
    const float* __restrict__ asw, const float* __restrict__ adw) {
    __shared__ float Ws[128 * 64];
    __shared__ float Xs[16 * 128];
    int t = threadIdx.x;
    for (int i = t; i < 128 * 64; i += 256) Ws[i] = W1[i];
    int n0 = blockIdx.x * 16;
    for (int i = t; i < 16 * 128; i += 256) {
        int nn = n0 + (i >> 7);
        Xs[i] = (nn < N_NODES) ? x[nn * 128 + (i & 127)] : 0.f;
    }
    __syncthreads();
    int c = t & 63, g = t >> 6;                 // node ni handled by 64 contiguous threads
    float a0 = 0, a1 = 0, a2 = 0, a3 = 0;
    const float* xs = &Xs[g * 4 * 128];
#pragma unroll 8
    for (int k = 0; k < 128; k++) {
        float w = Ws[k * 64 + c];
        a0 = fmaf(xs[k], w, a0);
        a1 = fmaf(xs[128 + k], w, a1);
        a2 = fmaf(xs[256 + k], w, a2);
        a3 = fmaf(xs[384 + k], w, a3);
    }
    float av = asw[c], dv = adw[c];             // att flattened [H*D]=64 matches channel c
    int h = c >> 5;
    float acc[4] = {a0, a1, a2, a3};
#pragma unroll
    for (int r = 0; r < 4; r++) {
        int node = n0 + g * 4 + r;
        float v = acc[r];
        float ps = v * av, pd = v * dv;
#pragma unroll
        for (int o = 16; o; o >>= 1) {
            ps += __shfl_xor_sync(0xffffffffu, ps, o);
            pd += __shfl_xor_sync(0xffffffffu, pd, o);
        }
        if (node < N_NODES) {
            g_xl1[node * 64 + c] = v;
            if ((c & 31) == 0) {                // lane 0 of each head's warp
                g_as1[node * 2 + h] = ps;
                g_ad1[node * 2 + h] = pd;
            }
        }
    }
}

// ---------------- layer 1 edge softmax + aggregate: one warp per dst node ----------------
__global__ void __launch_bounds__(256) k_edge1(const float* __restrict__ b1) {
    int wid = (blockIdx.x * blockDim.x + threadIdx.x) >> 5;
    int lane = threadIdx.x & 31;
    if (wid >= N_NODES) return;
    int dst = wid;
    int beg = g_rowptr[dst], end = g_rowptr[dst + 1];
    float2 adp = ((const float2*)g_ad1)[dst];
    float ad0 = adp.x, ad1 = adp.y;

    // pass 1: per-head max over incoming edges
    float m0 = -1e30f, m1 = -1e30f;
    for (int i = beg + lane; i < end; i += 32) {
        int s = g_csr[i];
        float2 as = ((const float2*)g_as1)[s];
        float e0 = as.x + ad0; e0 = e0 > 0.f ? e0 : 0.2f * e0;
        float e1 = as.y + ad1; e1 = e1 > 0.f ? e1 : 0.2f * e1;
        m0 = fmaxf(m0, e0);
        m1 = fmaxf(m1, e1);
    }
#pragma unroll
    for (int o = 16; o; o >>= 1) {
        m0 = fmaxf(m0, __shfl_xor_sync(0xffffffffu, m0, o));
        m1 = fmaxf(m1, __shfl_xor_sync(0xffffffffu, m1, o));
    }

    // pass 2: fused exp + denom + weighted aggregation (lane = channel)
    float acc0 = 0, acc1 = 0, den0 = 0, den1 = 0;
    for (int base = beg; base < end; base += 32) {
        int cnt = min(32, end - base);
        int sl = (lane < cnt) ? g_csr[base + lane] : 0;
        for (int j = 0; j < cnt; j++) {
            int s = __shfl_sync(0xffffffffu, sl, j);
            float2 as = ((const float2*)g_as1)[s];   // broadcast load
            float e0 = as.x + ad0; e0 = e0 > 0.f ? e0 : 0.2f * e0;
            float e1 = as.y + ad1; e1 = e1 > 0.f ? e1 : 0.2f * e1;
            float ex0 = __expf(e0 - m0);
            float ex1 = __expf(e1 - m1);
            den0 += ex0;
            den1 += ex1;
            const float* xr = &g_xl1[s * 64];
            acc0 = fmaf(ex0, xr[lane], acc0);
            acc1 = fmaf(ex1, xr[32 + lane], acc1);
        }
    }
    float o0 = acc0 / den0 + b1[lane];
    float o1 = acc1 / den1 + b1[32 + lane];
    o0 = o0 > 0.f ? o0 : expm1f(o0);            // ELU
    o1 = o1 > 0.f ? o1 : expm1f(o1);
    g_h1[dst * 64 + lane] = o0;
    g_h1[dst * 64 + 32 + lane] = o1;
}

// ---------------- layer 2 GEMM: xl2 = h1 @ W2 [N,64]x[64,128], + attn logits ----------------
__global__ void __launch_bounds__(256) k_gemm2(
    const float* __restrict__ W2,
    const float* __restrict__ asw, const float* __restrict__ adw) {
    __shared__ float Ws[64 * 128];
    __shared__ float Hs[8 * 64];
    __shared__ float sAS[8][4];
    __shared__ float sAD[8][4];
    int t = threadIdx.x;
    for (int i = t; i < 64 * 128; i += 256) Ws[i] = W2[i];
    int n0 = blockIdx.x * 8;
    for (int i = t; i < 8 * 64; i += 256) {
        int nn = n0 + (i >> 6);
        Hs[i] = (nn < N_NODES) ? g_h1[nn * 64 + (i & 63)] : 0.f;
    }
    __syncthreads();
    int c = t & 127, g = t >> 7;                // node handled by 128 contiguous threads
    float a[4] = {0, 0, 0, 0};
    const float* hs = &Hs[g * 4 * 64];
#pragma unroll 8
    for (int k = 0; k < 64; k++) {
        float w = Ws[k * 128 + c];
        a[0] = fmaf(hs[k], w, a[0]);
        a[1] = fmaf(hs[64 + k], w, a[1]);
        a[2] = fmaf(hs[128 + k], w, a[2]);
        a[3] = fmaf(hs[192 + k], w, a[3]);
    }
    float av = asw[c], dv = adw[c];
    int wim = (t >> 5) & 3;                     // warp within 128-thread node group
#pragma unroll
    for (int r = 0; r < 4; r++) {
        int node = n0 + g * 4 + r;
        float v = a[r];
        float ps = v * av, pd = v * dv;
#pragma unroll
        for (int o = 16; o; o >>= 1) {
            ps += __shfl_xor_sync(0xffffffffu, ps, o);
            pd += __shfl_xor_sync(0xffffffffu, pd, o);
        }
        if ((t & 31) == 0) {
            sAS[g * 4 + r][wim] = ps;
            sAD[g * 4 + r][wim] = pd;
        }
        if (node < N_NODES) g_xl2[node * 128 + c] = v;
    }
    __syncthreads();
    if (t < 8) {
        int node = n0 + t;
        if (node < N_NODES) {
            g_as2[node] = sAS[t][0] + sAS[t][1] + sAS[t][2] + sAS[t][3];
            g_ad2[node] = sAD[t][0] + sAD[t][1] + sAD[t][2] + sAD[t][3];
        }
    }
}

// ---------------- layer 2 edge softmax + aggregate + ELU + mean-pool scatter ----------------
__global__ void __launch_bounds__(256) k_edge2(const float* __restrict__ b2) {
    int wid = (blockIdx.x * blockDim.x + threadIdx.x) >> 5;
    int lane = threadIdx.x & 31;
    if (wid >= N_NODES) return;
    int dst = wid;
    int beg = g_rowptr[dst], end = g_rowptr[dst + 1];
    float ad = g_ad2[dst];

    float m = -1e30f;
    for (int i = beg + lane; i < end; i += 32) {
        int s = g_csr[i];
        float e = g_as2[s] + ad;
        e = e > 0.f ? e : 0.2f * e;
        m = fmaxf(m, e);
    }
#pragma unroll
    for (int o = 16; o; o >>= 1) m = fmaxf(m, __shfl_xor_sync(0xffffffffu, m, o));

    float acc0 = 0, acc1 = 0, acc2 = 0, acc3 = 0, den = 0;
    for (int base = beg; base < end; base += 32) {
        int cnt = min(32, end - base);
        int sl = (lane < cnt) ? g_csr[base + lane] : 0;
        for (int j = 0; j < cnt; j++) {
            int s = __shfl_sync(0xffffffffu, sl, j);
            float e = g_as2[s] + ad;
            e = e > 0.f ? e : 0.2f * e;
            float ex = __expf(e - m);
            den += ex;
            const float* xr = &g_xl2[s * 128];
            acc0 = fmaf(ex, xr[lane], acc0);
            acc1 = fmaf(ex, xr[32 + lane], acc1);
            acc2 = fmaf(ex, xr[64 + lane], acc2);
            acc3 = fmaf(ex, xr[96 + lane], acc3);
        }
    }
    float inv = 1.f / den;
    float o0 = acc0 * inv + b2[lane];       o0 = o0 > 0.f ? o0 : expm1f(o0);
    float o1 = acc1 * inv + b2[32 + lane];  o1 = o1 > 0.f ? o1 : expm1f(o1);
    float o2 = acc2 * inv + b2[64 + lane];  o2 = o2 > 0.f ? o2 : expm1f(o2);
    float o3 = acc3 * inv + b2[96 + lane];  o3 = o3 > 0.f ? o3 : expm1f(o3);

    float* p = &g_pool[g_batch[dst] * 128];
    atomicAdd(&p[lane], o0);
    atomicAdd(&p[32 + lane], o1);
    atomicAdd(&p[64 + lane], o2);
    atomicAdd(&p[96 + lane], o3);
}

// ---------------- finalize: mean pool ----------------
__global__ void k_final(float* __restrict__ out) {
    int i = blockIdx.x * blockDim.x + threadIdx.x;
    if (i >= N_GRAPHS * 128) return;
    float c = (float)g_cnt[i >> 7];
    out[i] = g_pool[i] / fmaxf(c, 1.f);
}

// ---------------- launch ----------------
extern "C" void kernel_launch(void* const* d_in, const int* in_sizes, int n_in,
                              void* d_out, int out_size) {
    const float* x   = (const float*)d_in[0];
    const void*  ei  = d_in[1];
    const void*  bat = d_in[2];
    const float* W1  = (const float*)d_in[3];
    const float* as1 = (const float*)d_in[4];
    const float* ad1 = (const float*)d_in[5];
    const float* b1  = (const float*)d_in[6];
    const float* W2  = (const float*)d_in[7];
    const float* as2 = (const float*)d_in[8];
    const float* ad2 = (const float*)d_in[9];
    const float* b2  = (const float*)d_in[10];
    float* out = (float*)d_out;

    k_detect<<<1, 256>>>((const int*)ei);
    k_init<<<(N_NODES + 255) / 256, 256>>>();
    k_edges<<<(N_EDGES + 255) / 256, 256>>>(ei);
    k_batch<<<(N_NODES + 255) / 256, 256>>>(bat);
    k_scan<<<1, 1024>>>();
    k_scatter<<<(E_TOT + 255) / 256, 256>>>();
    k_gemm1<<<(N_NODES + 15) / 16, 256>>>(x, W1, as1, ad1);
    k_edge1<<<(N_NODES * 32 + 255) / 256, 256>>>(b1);
    k_gemm2<<<(N_NODES + 7) / 8, 256>>>(W2, as2, ad2);
    k_edge2<<<(N_NODES * 32 + 255) / 256, 256>>>(b2);
    k_final<<<(N_GRAPHS * 128 + 255) / 256, 256>>>(out);
}